// round 14
// baseline (speedup 1.0000x reference)
#include <cuda_runtime.h>
#include <cuda_bf16.h>
#include <math.h>

#define T_STEPS 100000
#define S_DIM   200
#define N_DIM   215

// ---- device scratch (static; no runtime allocation) ----
__device__ float g_pre_f[T_STEPS * S_DIM];
__device__ float g_pre_i[T_STEPS * S_DIM];
__device__ float g_cand [T_STEPS * S_DIM];
__device__ float g_sfinal[S_DIM];

// ---- helpers ----
__device__ __forceinline__ unsigned smem_u32(const void* p) {
    unsigned a;
    asm("{ .reg .u64 t; cvta.to.shared.u64 t, %1; cvt.u32.u64 %0, t; }"
        : "=r"(a) : "l"(p));
    return a;
}
__device__ __forceinline__ unsigned mapa_u32(unsigned a, unsigned rank) {
    unsigned d;
    asm("mapa.shared::cluster.u32 %0, %1, %2;" : "=r"(d) : "r"(a), "r"(rank));
    return d;
}
__device__ __forceinline__ void st_shared_cluster_b64(unsigned addr,
                                                      unsigned long long v) {
    asm volatile("st.shared::cluster.b64 [%0], %1;"
                 :: "r"(addr), "l"(v) : "memory");
}
__device__ __forceinline__ unsigned long long ld_volatile_shared_b64(unsigned addr) {
    unsigned long long v;
    asm volatile("ld.volatile.shared.b64 %0, [%1];"
                 : "=l"(v) : "r"(addr) : "memory");
    return v;
}
__device__ __forceinline__ unsigned long long pack2(float x, float y) {
    unsigned long long r;
    asm("mov.b64 %0, {%1, %2};" : "=l"(r) : "f"(x), "f"(y));
    return r;
}
__device__ __forceinline__ float2 unpack2(unsigned long long v) {
    float2 f;
    asm("mov.b64 {%0, %1}, %2;" : "=f"(f.x), "=f"(f.y) : "l"(v));
    return f;
}
__device__ __forceinline__ unsigned long long tag_pack(unsigned tag, float val) {
    unsigned long long r;
    asm("mov.b64 %0, {%1, %2};" : "=l"(r) : "f"(val), "r"(tag));
    return r;  // lo = value, hi = tag
}
#define FMA2(acc, a, b) \
    asm("fma.rn.f32x2 %0, %1, %2, %0;" : "+l"(acc) : "l"(a), "l"(b))
#define ADD2(out, a, b) \
    asm("add.rn.f32x2 %0, %1, %2;" : "=l"(out) : "l"(a), "l"(b))

#define CLUSTER_ARRIVE() \
    asm volatile("barrier.cluster.arrive.aligned;" ::: "memory")
#define CLUSTER_WAIT() \
    asm volatile("barrier.cluster.wait.aligned;" ::: "memory")

// ============================================================
// Phase 1: the three track GEMMs. grid (3125,3), block 256.
// ============================================================
#define TILE_T 32
#define KCHUNK 43   // 5*43 = 215

__global__ __launch_bounds__(256) void pre_kernel(
    const float* __restrict__ track,
    const float* __restrict__ Wf, const float* __restrict__ bf,
    const float* __restrict__ Wi, const float* __restrict__ bi,
    const float* __restrict__ Wc, const float* __restrict__ bc)
{
    __shared__ float sW[KCHUNK * S_DIM];
    __shared__ float sT[TILE_T * KCHUNK];
    const int mat = blockIdx.y;
    const int t0  = blockIdx.x * TILE_T;
    const int tid = threadIdx.x;
    const float* W   = (mat == 0) ? Wf : (mat == 1) ? Wi : Wc;
    const float* bia = (mat == 0) ? bf : (mat == 1) ? bi : bc;
    float* out       = (mat == 0) ? g_pre_f : (mat == 1) ? g_pre_i : g_cand;

    float acc[TILE_T];
    #pragma unroll
    for (int i = 0; i < TILE_T; i++) acc[i] = 0.0f;

    for (int c = 0; c < 5; c++) {
        const int k0 = c * KCHUNK;
        for (int idx = tid; idx < KCHUNK * S_DIM; idx += 256) {
            int r = idx / S_DIM, col = idx - r * S_DIM;
            sW[idx] = W[(k0 + r) * S_DIM + col];
        }
        for (int idx = tid; idx < TILE_T * KCHUNK; idx += 256) {
            int tt = idx / KCHUNK, kk = idx - tt * KCHUNK;
            sT[idx] = track[(t0 + tt) * N_DIM + k0 + kk];
        }
        __syncthreads();
        if (tid < S_DIM) {
            for (int kk = 0; kk < KCHUNK; kk++) {
                float wv = sW[kk * S_DIM + tid];
                #pragma unroll
                for (int tt = 0; tt < TILE_T; tt++)
                    acc[tt] = fmaf(sT[tt * KCHUNK + kk], wv, acc[tt]);
            }
        }
        __syncthreads();
    }
    if (tid < S_DIM) {
        float bv = bia[tid];
        #pragma unroll 4
        for (int tt = 0; tt < TILE_T; tt++) {
            float v = acc[tt] + bv;
            if (mat == 2) v = tanhf(v);
            out[(t0 + tt) * S_DIM + tid] = v;
        }
    }
}

// ============================================================
// Phase 2: sequential scan. 4-CTA cluster, 224 threads/CTA.
// CTA r: gate g=r>>1 (0:f->u, 1:i->v), column half hf=r&1.
// Each CTA computes FULL-k z for its 100 columns (20K MACs),
// gates, and pushes its 100 tagged contributions to the 3 peers'
// inboxes (R13's proven primitive: remote st.shared::cluster b64,
// data is its own flag, local volatile polls, parity buffers,
// monotonic tags). Every CTA assembles the full replicated state:
//   my-half col:    local contrib + poll(in_same  <- rank^2)
//   other-half col: poll(in_o1 <- rank^1) + poll(in_o2 <- rank^3)
// Deterministic (same adds everywhere); lockstep (each CTA needs
// all 3 peers per step => skew<=1); no rendezvous in the loop.
// ============================================================
__global__ void __cluster_dims__(4, 1, 1) __launch_bounds__(224, 1)
scan_kernel(const float* __restrict__ Wf, const float* __restrict__ Wi,
            const float* __restrict__ state0)
{
    __shared__ __align__(16) float s_state[S_DIM];
    __shared__ __align__(16) unsigned long long s_in_same[2][100];
    __shared__ __align__(16) unsigned long long s_in_o1[2][100];
    __shared__ __align__(16) unsigned long long s_in_o2[2][100];

    const int tid = threadIdx.x;
    unsigned rank;
    asm("mov.u32 %0, %%cluster_ctarank;" : "=r"(rank));

    const int g  = (int)(rank >> 1);   // 0: f-gate (u), 1: i-gate (v)
    const int hf = (int)(rank & 1);    // column half

    const bool act = (tid < 200);
    const int  jl  = act ? (tid >> 1) : 0;   // local column 0..99
    const int  h   = tid & 1;                // k-half
    const bool own = act && (h == 0);
    const int  Gm  = hf * 100 + jl;          // my global column
    const int  Go  = (1 - hf) * 100 + jl;    // other-half global column

    // ---- weights: column Gm of my gate matrix, k-half h ----
    const float* W = (g == 0) ? Wf : Wi;     // rows [215,415) = recurrent
    const int kbase = N_DIM + h * 100;
    unsigned long long w[50];
    #pragma unroll
    for (int i = 0; i < 50; i++) {
        float a = act ? W[(kbase + 2 * i    ) * S_DIM + Gm] : 0.0f;
        float b = act ? W[(kbase + 2 * i + 1) * S_DIM + Gm] : 0.0f;
        w[i] = pack2(a, b);
    }

    // init: replicated state + zeroed inboxes
    if (tid < S_DIM) s_state[tid] = state0[tid];
    if (tid < 100) {
        s_in_same[0][tid] = 0ull; s_in_same[1][tid] = 0ull;
        s_in_o1[0][tid] = 0ull;   s_in_o1[1][tid] = 0ull;
        s_in_o2[0][tid] = 0ull;   s_in_o2[1][tid] = 0ull;
    }
    __syncthreads();
    CLUSTER_ARRIVE();   // one-time: init visible cluster-wide before pushes
    CLUSTER_WAIT();

    // push targets: my contrib for column jl goes to
    //   (rank^2).in_same[p][jl], (rank^1).in_o1[p][jl], (rank^3).in_o2[p][jl]
    const int jj = own ? jl : 0;
    unsigned pA[2], pB[2], pC[2], lS[2], l1[2], l2[2];
    #pragma unroll
    for (int p = 0; p < 2; p++) {
        pA[p] = mapa_u32(smem_u32(&s_in_same[p][jj]), rank ^ 2u);
        pB[p] = mapa_u32(smem_u32(&s_in_o1[p][jj]),   rank ^ 1u);
        pC[p] = mapa_u32(smem_u32(&s_in_o2[p][jj]),   rank ^ 3u);
        lS[p] = smem_u32(&s_in_same[p][jj]);
        l1[p] = smem_u32(&s_in_o1[p][jj]);
        l2[p] = smem_u32(&s_in_o2[p][jj]);
    }

    const float* pre = (g == 0) ? g_pre_f : g_pre_i;
    float p_cur = 0.0f, c_cur = 0.0f;
    if (own) {
        p_cur = __ldcg(pre + Gm);
        if (g == 1) c_cur = __ldcg(g_cand + Gm);
    }

    for (int t = 0; t < T_STEPS; t++) {
        const int b = t & 1;

        // prefetch next step's streams (hides DRAM latency)
        float p_next = 0.0f, c_next = 0.0f;
        if (own) {
            int tn = (t + 1 < T_STEPS) ? (t + 1) : (T_STEPS - 1);
            p_next = __ldcg(pre + tn * S_DIM + Gm);
            if (g == 1) c_next = __ldcg(g_cand + tn * S_DIM + Gm);
        }

        // ---- matvec: 100 MACs/thread as 50 packed f32x2 FMAs ----
        unsigned long long a0 = 0ull, a1 = 0ull;
        const ulonglong2* s4 = (const ulonglong2*)s_state + h * 25;
        #pragma unroll
        for (int i = 0; i < 25; i++) {
            ulonglong2 sv = s4[i];
            FMA2(a0, w[2 * i    ], sv.x);
            FMA2(a1, w[2 * i + 1], sv.y);
        }
        unsigned long long r01;
        ADD2(r01, a0, a1);
        float2 f = unpack2(r01);
        float zp = f.x + f.y;
        float z  = zp + __shfl_xor_sync(0xFFFFFFFFu, zp, 1);

        if (own) {
            z += p_cur;
            float gg = __fdividef(1.0f, 1.0f + __expf(-z));
            float contrib = (g == 0) ? (s_state[Gm] * gg) : (gg * c_cur);

            // push my contribution to all 3 peers (fire-and-forget)
            const unsigned tag = (unsigned)(t + 1);
            unsigned long long pkt = tag_pack(tag, contrib);
            st_shared_cluster_b64(pA[b], pkt);
            st_shared_cluster_b64(pB[b], pkt);
            st_shared_cluster_b64(pC[b], pkt);

            // assemble my-half column: contrib + other-gate same-half
            unsigned long long q = ld_volatile_shared_b64(lS[b]);
            while ((unsigned)(q >> 32) != tag)
                q = ld_volatile_shared_b64(lS[b]);
            s_state[Gm] = contrib + __uint_as_float((unsigned)q);

            // assemble other-half column: two foreign contribs
            unsigned long long q1 = ld_volatile_shared_b64(l1[b]);
            while ((unsigned)(q1 >> 32) != tag)
                q1 = ld_volatile_shared_b64(l1[b]);
            unsigned long long q2 = ld_volatile_shared_b64(l2[b]);
            while ((unsigned)(q2 >> 32) != tag)
                q2 = ld_volatile_shared_b64(l2[b]);
            s_state[Go] = __uint_as_float((unsigned)q1)
                        + __uint_as_float((unsigned)q2);
        }
        __syncthreads();

        p_cur = p_next; c_cur = c_next;
    }

    if (rank == 0 && tid < S_DIM) g_sfinal[tid] = s_state[tid];
    // exit sync: no CTA may die while a peer might still push into it
    CLUSTER_ARRIVE();
    CLUSTER_WAIT();
}

// ============================================================
// Phase 3: output head. 1 block, 256 threads.
// ============================================================
__global__ __launch_bounds__(256) void head_kernel(
    const float* __restrict__ W1, const float* __restrict__ b1,
    const float* __restrict__ W2, const float* __restrict__ b2,
    float* __restrict__ out)
{
    __shared__ float s_s[S_DIM], s_h[S_DIM], s_red[256];
    const int tid = threadIdx.x;
    if (tid < S_DIM) s_s[tid] = g_sfinal[tid];
    __syncthreads();

    if (tid < S_DIM) {
        float a = b1[tid];
        for (int k = 0; k < S_DIM; k++) a = fmaf(s_s[k], W1[k * S_DIM + tid], a);
        s_h[tid] = fmaxf(a, 0.0f);
    }
    __syncthreads();
    float h2 = 0.0f;
    if (tid < S_DIM) {
        float a = b2[tid];
        for (int k = 0; k < S_DIM; k++) a = fmaf(s_h[k], W2[k * S_DIM + tid], a);
        h2 = fmaxf(a, 0.0f);
    }
    s_red[tid] = (tid < S_DIM) ? h2 : -1e30f;
    __syncthreads();
    for (int s = 128; s > 0; s >>= 1) {
        if (tid < s) s_red[tid] = fmaxf(s_red[tid], s_red[tid + s]);
        __syncthreads();
    }
    float m = s_red[0];
    __syncthreads();
    s_red[tid] = (tid < S_DIM) ? expf(h2 - m) : 0.0f;
    __syncthreads();
    for (int s = 128; s > 0; s >>= 1) {
        if (tid < s) s_red[tid] += s_red[tid + s];
        __syncthreads();
    }
    float lse = logf(s_red[0]);
    if (tid < S_DIM) out[tid] = h2 - m - lse;
}

// ============================================================
extern "C" void kernel_launch(void* const* d_in, const int* in_sizes, int n_in,
                              void* d_out, int out_size) {
    const float* track  = (const float*)d_in[0];
    const float* state0 = (const float*)d_in[1];
    const float* Wf     = (const float*)d_in[2];
    const float* bf     = (const float*)d_in[3];
    const float* Wi     = (const float*)d_in[4];
    const float* bi     = (const float*)d_in[5];
    const float* Wc     = (const float*)d_in[6];
    const float* bc     = (const float*)d_in[7];
    const float* W1     = (const float*)d_in[8];
    const float* b1     = (const float*)d_in[9];
    const float* W2     = (const float*)d_in[10];
    const float* b2     = (const float*)d_in[11];
    float* out = (float*)d_out;

    dim3 g(T_STEPS / TILE_T, 3);
    pre_kernel<<<g, 256>>>(track, Wf, bf, Wi, bi, Wc, bc);
    scan_kernel<<<4, 224>>>(Wf, Wi, state0);
    head_kernel<<<1, 256>>>(W1, b1, W2, b2, out);
}